// round 3
// baseline (speedup 1.0000x reference)
#include <cuda_runtime.h>
#include <cuda_bf16.h>

// out[b,0,h,w] = sum_c x[b,c,h,w] * wq[c] + bias
// x: (8,128,512,512) f32, W: 128 f32 (quant-dequant to int8 grid), b: 1 f32
// Pure HBM-bound streaming reduction over channel dim.
// Traffic: 1 GiB read + 8 MiB write -> roofline ~165-185 us on GB300.

#define C_CH   128
#define HW     (512 * 512)        // 262144 elems per plane
#define HW4    (HW / 4)           // 65536 float4 per plane
#define BATCH  8

__device__ float g_wq[C_CH];

// ---------------------------------------------------------------------------
// Prologue: quant-dequant the 128-element weight vector.
//   scale = max|W| / 127 ; wq = clip(rint(W/scale), -127, 127) * scale
// ---------------------------------------------------------------------------
__global__ void quant_weights_kernel(const float* __restrict__ W) {
    __shared__ float red[C_CH];
    int t = threadIdx.x;
    float w = W[t];
    red[t] = fabsf(w);
    __syncthreads();
    #pragma unroll
    for (int s = 64; s > 0; s >>= 1) {
        if (t < s) red[t] = fmaxf(red[t], red[t + s]);
        __syncthreads();
    }
    float scale = red[0] / 127.0f;
    float q = rintf(w / scale);              // round-half-even, matches jnp.round
    q = fminf(fmaxf(q, -127.0f), 127.0f);
    g_wq[t] = q * scale;
}

// ---------------------------------------------------------------------------
// Main: each thread produces one float4 of output (4 spatial positions),
// streaming 128 channel planes with LDG.128. 2048 blocks x 256 threads.
// Two independent accumulator chains (channel halves) so ptxas can
// front-batch loads and break the FMA RAW chain.
// ---------------------------------------------------------------------------
__global__ __launch_bounds__(256) void channel_reduce_kernel(
    const float* __restrict__ x,
    const float* __restrict__ bias,
    float* __restrict__ out)
{
    __shared__ float ws[C_CH];
    int t = threadIdx.x;
    if (t < C_CH) ws[t] = g_wq[t];

    float bb = bias[0];                       // hoisted; overlaps the loop
    __syncthreads();

    int o4 = blockIdx.x * blockDim.x + t;     // 0 .. 8*65536-1
    int b  = o4 >> 16;                        // o4 / HW4
    int s4 = o4 & (HW4 - 1);                  // o4 % HW4

    const float4* xp = reinterpret_cast<const float4*>(x)
                     + (size_t)b * (C_CH * HW4) + s4;

    float ax0 = 0.f, ay0 = 0.f, az0 = 0.f, aw0 = 0.f;
    float ax1 = 0.f, ay1 = 0.f, az1 = 0.f, aw1 = 0.f;

    #pragma unroll 8
    for (int c = 0; c < C_CH / 2; ++c) {
        float4 v0 = __ldg(xp + (size_t)c * HW4);
        float4 v1 = __ldg(xp + (size_t)(c + C_CH / 2) * HW4);
        float w0 = ws[c];
        float w1 = ws[c + C_CH / 2];
        ax0 = fmaf(v0.x, w0, ax0);
        ay0 = fmaf(v0.y, w0, ay0);
        az0 = fmaf(v0.z, w0, az0);
        aw0 = fmaf(v0.w, w0, aw0);
        ax1 = fmaf(v1.x, w1, ax1);
        ay1 = fmaf(v1.y, w1, ay1);
        az1 = fmaf(v1.z, w1, az1);
        aw1 = fmaf(v1.w, w1, aw1);
    }

    float4 r;
    r.x = ax0 + ax1 + bb;
    r.y = ay0 + ay1 + bb;
    r.z = az0 + az1 + bb;
    r.w = aw0 + aw1 + bb;
    reinterpret_cast<float4*>(out)[o4] = r;
}

extern "C" void kernel_launch(void* const* d_in, const int* in_sizes, int n_in,
                              void* d_out, int out_size) {
    const float* x    = (const float*)d_in[0];
    const float* W    = (const float*)d_in[1];
    const float* bias = (const float*)d_in[2];
    float* out        = (float*)d_out;

    quant_weights_kernel<<<1, C_CH>>>(W);

    int total4 = BATCH * HW4;                 // 524288
    int threads = 256;
    int blocks = total4 / threads;            // 2048
    channel_reduce_kernel<<<blocks, threads>>>(x, bias, out);
}

// round 6
// speedup vs baseline: 1.0395x; 1.0395x over previous
#include <cuda_runtime.h>
#include <cuda_bf16.h>

// out[b,0,h,w] = sum_c x[b,c,h,w] * wq[c] + bias
// x: (8,128,512,512) f32, W: 128 f32 (quant-dequant to int8 grid), b: 1 f32
// Pure HBM-bound streaming reduction over channel dim.
// R3: 172.8us @ DRAM 80.3% (2048 blocks, ~2 waves).
// R4: single balanced wave — 1024 persistent blocks x 2 tiles each.

#define C_CH   128
#define HW     (512 * 512)        // 262144 elems per plane
#define HW4    (HW / 4)           // 65536 float4 per plane
#define BATCH  8
#define NBLK   1024               // < 1036 (=148 SMs * 7 blocks @36regs) -> one wave
#define NTILE  2                  // 2048 tiles total / NBLK

__device__ float g_wq[C_CH];

// ---------------------------------------------------------------------------
// Prologue: quant-dequant the 128-element weight vector.
//   scale = max|W| / 127 ; wq = clip(rint(W/scale), -127, 127) * scale
// ---------------------------------------------------------------------------
__global__ void quant_weights_kernel(const float* __restrict__ W) {
    __shared__ float red[C_CH];
    int t = threadIdx.x;
    float w = W[t];
    red[t] = fabsf(w);
    __syncthreads();
    #pragma unroll
    for (int s = 64; s > 0; s >>= 1) {
        if (t < s) red[t] = fmaxf(red[t], red[t + s]);
        __syncthreads();
    }
    float scale = red[0] / 127.0f;
    float q = rintf(w / scale);              // round-half-even, matches jnp.round
    q = fminf(fmaxf(q, -127.0f), 127.0f);
    g_wq[t] = q * scale;
}

// ---------------------------------------------------------------------------
// Main: 1024 blocks x 256 threads, each thread produces 2 output float4s
// (tiles blockIdx and blockIdx+1024), processed sequentially so regs stay
// at ~36 and all blocks are co-resident in ONE wave. Inner loop streams the
// 128 channel planes as two independent LDG.128 + FMA chains.
// ---------------------------------------------------------------------------
__global__ __launch_bounds__(256) void channel_reduce_kernel(
    const float* __restrict__ x,
    const float* __restrict__ bias,
    float* __restrict__ out)
{
    __shared__ float ws[C_CH];
    int t = threadIdx.x;
    if (t < C_CH) ws[t] = g_wq[t];

    float bb = bias[0];                       // hoisted; overlaps the loop
    __syncthreads();

    #pragma unroll
    for (int tile = 0; tile < NTILE; ++tile) {
        int o4 = (blockIdx.x + tile * NBLK) * blockDim.x + t;  // 0..524287
        int b  = o4 >> 16;                    // o4 / HW4
        int s4 = o4 & (HW4 - 1);              // o4 % HW4

        const float4* xp = reinterpret_cast<const float4*>(x)
                         + (size_t)b * (C_CH * HW4) + s4;

        float ax0 = 0.f, ay0 = 0.f, az0 = 0.f, aw0 = 0.f;
        float ax1 = 0.f, ay1 = 0.f, az1 = 0.f, aw1 = 0.f;

        #pragma unroll 8
        for (int c = 0; c < C_CH / 2; ++c) {
            float4 v0 = __ldg(xp + (size_t)c * HW4);
            float4 v1 = __ldg(xp + (size_t)(c + C_CH / 2) * HW4);
            float w0 = ws[c];
            float w1 = ws[c + C_CH / 2];
            ax0 = fmaf(v0.x, w0, ax0);
            ay0 = fmaf(v0.y, w0, ay0);
            az0 = fmaf(v0.z, w0, az0);
            aw0 = fmaf(v0.w, w0, aw0);
            ax1 = fmaf(v1.x, w1, ax1);
            ay1 = fmaf(v1.y, w1, ay1);
            az1 = fmaf(v1.z, w1, az1);
            aw1 = fmaf(v1.w, w1, aw1);
        }

        float4 r;
        r.x = ax0 + ax1 + bb;
        r.y = ay0 + ay1 + bb;
        r.z = az0 + az1 + bb;
        r.w = aw0 + aw1 + bb;
        reinterpret_cast<float4*>(out)[o4] = r;
    }
}

extern "C" void kernel_launch(void* const* d_in, const int* in_sizes, int n_in,
                              void* d_out, int out_size) {
    const float* x    = (const float*)d_in[0];
    const float* W    = (const float*)d_in[1];
    const float* bias = (const float*)d_in[2];
    float* out        = (float*)d_out;

    quant_weights_kernel<<<1, C_CH>>>(W);

    channel_reduce_kernel<<<NBLK, 256>>>(x, bias, out);
}

// round 8
// speedup vs baseline: 1.0772x; 1.0363x over previous
#include <cuda_runtime.h>
#include <cuda_bf16.h>

// out[b,0,h,w] = sum_c x[b,c,h,w] * wq[c] + bias
// x: (8,128,512,512) f32, W: 128 f32 (quant-dequant to int8 grid), b: 1 f32
// Pure HBM-bound streaming reduction over channel dim.
// R3: 172.8us @ DRAM 80.3% (2048 blocks, ~2 waves).
// R6: 166.2us @ DRAM 84.8% (1024 blocks but regs=42 -> 6/SM -> ragged wave).
// R7: fuse quant prologue into main kernel (kill 5us launch bubble) +
//     __launch_bounds__(256,7) to force 36 regs -> 7/SM -> true single wave.

#define C_CH   128
#define HW     (512 * 512)        // 262144 elems per plane
#define HW4    (HW / 4)           // 65536 float4 per plane
#define BATCH  8
#define NBLK   1024               // <= 1064 (=152 SMs * 7 blocks @36regs) -> one wave
#define NTILE  2                  // 2048 tiles total / NBLK

// ---------------------------------------------------------------------------
// Fused kernel: each block (redundantly) quant-dequants the 128-element W
// vector into shared memory (512B from L2, ~300 cyc), then streams its two
// output tiles. 1024 blocks x 256 threads, one wave.
// ---------------------------------------------------------------------------
__global__ __launch_bounds__(256, 7) void channel_reduce_fused_kernel(
    const float* __restrict__ x,
    const float* __restrict__ W,
    const float* __restrict__ bias,
    float* __restrict__ out)
{
    __shared__ float ws[C_CH];
    __shared__ float red[C_CH];
    int t = threadIdx.x;

    // --- inline quant-dequant: scale = max|W|/127; wq = clip(rint(W/scale))*scale
    float w = 0.f;
    if (t < C_CH) {
        w = W[t];
        red[t] = fabsf(w);
    }
    __syncthreads();
    #pragma unroll
    for (int s = 64; s > 0; s >>= 1) {
        if (t < s) red[t] = fmaxf(red[t], red[t + s]);
        __syncthreads();
    }
    if (t < C_CH) {
        float scale = red[0] / 127.0f;
        float q = rintf(w / scale);          // round-half-even, matches jnp.round
        q = fminf(fmaxf(q, -127.0f), 127.0f);
        ws[t] = q * scale;
    }
    float bb = bias[0];
    __syncthreads();

    // --- streaming channel reduction, 2 tiles per block, sequential
    #pragma unroll
    for (int tile = 0; tile < NTILE; ++tile) {
        int o4 = (blockIdx.x + tile * NBLK) * blockDim.x + t;  // 0..524287
        int b  = o4 >> 16;                    // o4 / HW4
        int s4 = o4 & (HW4 - 1);              // o4 % HW4

        const float4* xp = reinterpret_cast<const float4*>(x)
                         + (size_t)b * (C_CH * HW4) + s4;

        float ax0 = 0.f, ay0 = 0.f, az0 = 0.f, aw0 = 0.f;
        float ax1 = 0.f, ay1 = 0.f, az1 = 0.f, aw1 = 0.f;

        #pragma unroll 8
        for (int c = 0; c < C_CH / 2; ++c) {
            float4 v0 = __ldg(xp + (size_t)c * HW4);
            float4 v1 = __ldg(xp + (size_t)(c + C_CH / 2) * HW4);
            float w0 = ws[c];
            float w1 = ws[c + C_CH / 2];
            ax0 = fmaf(v0.x, w0, ax0);
            ay0 = fmaf(v0.y, w0, ay0);
            az0 = fmaf(v0.z, w0, az0);
            aw0 = fmaf(v0.w, w0, aw0);
            ax1 = fmaf(v1.x, w1, ax1);
            ay1 = fmaf(v1.y, w1, ay1);
            az1 = fmaf(v1.z, w1, az1);
            aw1 = fmaf(v1.w, w1, aw1);
        }

        float4 r;
        r.x = ax0 + ax1 + bb;
        r.y = ay0 + ay1 + bb;
        r.z = az0 + az1 + bb;
        r.w = aw0 + aw1 + bb;
        reinterpret_cast<float4*>(out)[o4] = r;
    }
}

extern "C" void kernel_launch(void* const* d_in, const int* in_sizes, int n_in,
                              void* d_out, int out_size) {
    const float* x    = (const float*)d_in[0];
    const float* W    = (const float*)d_in[1];
    const float* bias = (const float*)d_in[2];
    float* out        = (float*)d_out;

    channel_reduce_fused_kernel<<<NBLK, 256>>>(x, W, bias, out);
}

// round 9
// speedup vs baseline: 1.0813x; 1.0038x over previous
#include <cuda_runtime.h>
#include <cuda_bf16.h>

// out[b,0,h,w] = sum_c x[b,c,h,w] * wq[c] + bias
// x: (8,128,512,512) f32, W: 128 f32 (quant-dequant to int8 grid), b: 1 f32
// Pure HBM-bound streaming reduction over channel dim.
// R3: 172.8us @ DRAM 80.3% (2048 blocks, ~2 waves).
// R6: 166.2us @ DRAM 84.8% (1024 blocks but regs=42 -> 6/SM -> ragged wave).
// R7: fuse quant prologue into main kernel (kill 5us launch bubble) +
//     __launch_bounds__(256,7) to force 36 regs -> 7/SM -> true single wave.

#define C_CH   128
#define HW     (512 * 512)        // 262144 elems per plane
#define HW4    (HW / 4)           // 65536 float4 per plane
#define BATCH  8
#define NBLK   1024               // <= 1064 (=152 SMs * 7 blocks @36regs) -> one wave
#define NTILE  2                  // 2048 tiles total / NBLK

// ---------------------------------------------------------------------------
// Fused kernel: each block (redundantly) quant-dequants the 128-element W
// vector into shared memory (512B from L2, ~300 cyc), then streams its two
// output tiles. 1024 blocks x 256 threads, one wave.
// ---------------------------------------------------------------------------
__global__ __launch_bounds__(256, 7) void channel_reduce_fused_kernel(
    const float* __restrict__ x,
    const float* __restrict__ W,
    const float* __restrict__ bias,
    float* __restrict__ out)
{
    __shared__ float ws[C_CH];
    __shared__ float red[C_CH];
    int t = threadIdx.x;

    // --- inline quant-dequant: scale = max|W|/127; wq = clip(rint(W/scale))*scale
    float w = 0.f;
    if (t < C_CH) {
        w = W[t];
        red[t] = fabsf(w);
    }
    __syncthreads();
    #pragma unroll
    for (int s = 64; s > 0; s >>= 1) {
        if (t < s) red[t] = fmaxf(red[t], red[t + s]);
        __syncthreads();
    }
    if (t < C_CH) {
        float scale = red[0] / 127.0f;
        float q = rintf(w / scale);          // round-half-even, matches jnp.round
        q = fminf(fmaxf(q, -127.0f), 127.0f);
        ws[t] = q * scale;
    }
    float bb = bias[0];
    __syncthreads();

    // --- streaming channel reduction, 2 tiles per block, sequential
    #pragma unroll
    for (int tile = 0; tile < NTILE; ++tile) {
        int o4 = (blockIdx.x + tile * NBLK) * blockDim.x + t;  // 0..524287
        int b  = o4 >> 16;                    // o4 / HW4
        int s4 = o4 & (HW4 - 1);              // o4 % HW4

        const float4* xp = reinterpret_cast<const float4*>(x)
                         + (size_t)b * (C_CH * HW4) + s4;

        float ax0 = 0.f, ay0 = 0.f, az0 = 0.f, aw0 = 0.f;
        float ax1 = 0.f, ay1 = 0.f, az1 = 0.f, aw1 = 0.f;

        #pragma unroll 8
        for (int c = 0; c < C_CH / 2; ++c) {
            float4 v0 = __ldg(xp + (size_t)c * HW4);
            float4 v1 = __ldg(xp + (size_t)(c + C_CH / 2) * HW4);
            float w0 = ws[c];
            float w1 = ws[c + C_CH / 2];
            ax0 = fmaf(v0.x, w0, ax0);
            ay0 = fmaf(v0.y, w0, ay0);
            az0 = fmaf(v0.z, w0, az0);
            aw0 = fmaf(v0.w, w0, aw0);
            ax1 = fmaf(v1.x, w1, ax1);
            ay1 = fmaf(v1.y, w1, ay1);
            az1 = fmaf(v1.z, w1, az1);
            aw1 = fmaf(v1.w, w1, aw1);
        }

        float4 r;
        r.x = ax0 + ax1 + bb;
        r.y = ay0 + ay1 + bb;
        r.z = az0 + az1 + bb;
        r.w = aw0 + aw1 + bb;
        reinterpret_cast<float4*>(out)[o4] = r;
    }
}

extern "C" void kernel_launch(void* const* d_in, const int* in_sizes, int n_in,
                              void* d_out, int out_size) {
    const float* x    = (const float*)d_in[0];
    const float* W    = (const float*)d_in[1];
    const float* bias = (const float*)d_in[2];
    float* out        = (float*)d_out;

    channel_reduce_fused_kernel<<<NBLK, 256>>>(x, W, bias, out);
}